// round 1
// baseline (speedup 1.0000x reference)
#include <cuda_runtime.h>
#include <math.h>

// ---------------- problem constants ----------------
constexpr int B_  = 8;
constexpr int S_  = 512;
constexpr int E_  = 384;
constexpr int H_  = 7;
constexpr int D_  = 54;
constexpr int L_  = 7;
constexpr int V_  = 32000;
constexpr int FF_ = 6 * E_;          // 2304
constexpr int BS_ = B_ * S_;         // 4096
constexpr int HD_ = H_ * D_;         // 378
constexpr float EPS_ = 1e-5f;

// ---------------- scratch (static device memory; no allocation) ----------------
__device__ float g_x   [BS_ * E_];                 // residual stream
__device__ float g_xn  [BS_ * E_];                 // layernorm output
__device__ float g_q   [H_ * BS_ * D_];            // q (later reused as o_head)
__device__ float g_k   [H_ * BS_ * D_];
__device__ float g_v   [H_ * BS_ * D_];
__device__ float g_attn[(size_t)H_ * B_ * S_ * S_];// attention probs
__device__ float g_ocat[BS_ * HD_];                // concatenated heads
__device__ float g_h   [BS_ * FF_];                // FF hidden
__device__ float g_loss;

// ---------------- flags for the generic GEMM ----------------
#define FLAG_TRANSB 1
#define FLAG_ACC    2
#define FLAG_GELU   4

__device__ __forceinline__ float gelu_f(float x) {
    // exact gelu: x * 0.5 * (1 + erf(x / sqrt(2)))
    return 0.5f * x * (1.0f + erff(x * 0.70710678118654752f));
}

// Generic batched SGEMM: C = alpha * A @ B (+ bias) (+ C if FLAG_ACC), optional GELU.
// A: [M,K] lda row-major. B: [K,N] ldb (or [N,K] ldb if FLAG_TRANSB). C: [M,N] ldc.
// blockIdx.z = batch; per-batch pointer strides sA/sB/sBias/sC.
__global__ void __launch_bounds__(256)
sgemm_kernel(const float* __restrict__ A, const float* __restrict__ Bm,
             const float* __restrict__ bias, float* __restrict__ C,
             int M, int N, int K, int lda, int ldb, int ldc,
             long long sA, long long sB, long long sBias, long long sC,
             float alpha, int flags)
{
    __shared__ float As[16][64];
    __shared__ float Bs[16][64];

    const int z = blockIdx.z;
    A += (long long)z * sA;
    Bm += (long long)z * sB;
    C += (long long)z * sC;
    if (bias) bias += (long long)z * sBias;

    const int row0 = blockIdx.y * 64;
    const int col0 = blockIdx.x * 64;
    const int tid = threadIdx.x;
    const int ty = tid >> 4;       // 0..15
    const int tx = tid & 15;       // 0..15

    float acc[4][4];
#pragma unroll
    for (int i = 0; i < 4; i++)
#pragma unroll
        for (int j = 0; j < 4; j++) acc[i][j] = 0.f;

    for (int k0 = 0; k0 < K; k0 += 16) {
        // load A tile (store transposed: As[k][m])
#pragma unroll
        for (int t = tid; t < 64 * 16; t += 256) {
            int r = t >> 4, c = t & 15;
            int gr = row0 + r, gc = k0 + c;
            As[c][r] = (gr < M && gc < K) ? A[(long long)gr * lda + gc] : 0.f;
        }
        if (flags & FLAG_TRANSB) {
#pragma unroll
            for (int t = tid; t < 64 * 16; t += 256) {
                int n = t >> 4, c = t & 15;
                int gn = col0 + n, gc = k0 + c;
                Bs[c][n] = (gn < N && gc < K) ? Bm[(long long)gn * ldb + gc] : 0.f;
            }
        } else {
#pragma unroll
            for (int t = tid; t < 16 * 64; t += 256) {
                int c = t >> 6, n = t & 63;
                int gc = k0 + c, gn = col0 + n;
                Bs[c][n] = (gc < K && gn < N) ? Bm[(long long)gc * ldb + gn] : 0.f;
            }
        }
        __syncthreads();

#pragma unroll
        for (int kk = 0; kk < 16; kk++) {
            float a[4], b[4];
#pragma unroll
            for (int i = 0; i < 4; i++) a[i] = As[kk][ty * 4 + i];
#pragma unroll
            for (int j = 0; j < 4; j++) b[j] = Bs[kk][tx * 4 + j];
#pragma unroll
            for (int i = 0; i < 4; i++)
#pragma unroll
                for (int j = 0; j < 4; j++) acc[i][j] = fmaf(a[i], b[j], acc[i][j]);
        }
        __syncthreads();
    }

#pragma unroll
    for (int i = 0; i < 4; i++) {
        int r = row0 + ty * 4 + i;
        if (r >= M) continue;
#pragma unroll
        for (int j = 0; j < 4; j++) {
            int c = col0 + tx * 4 + j;
            if (c >= N) continue;
            float vv = acc[i][j] * alpha;
            if (bias) vv += bias[c];
            if (flags & FLAG_GELU) vv = gelu_f(vv);
            long long ci = (long long)r * ldc + c;
            if (flags & FLAG_ACC) vv += C[ci];
            C[ci] = vv;
        }
    }
}

// x[row,:] = tok_emb[ids[row],:] + pos_emb[row % S,:]
__global__ void embed_kernel(const int* __restrict__ ids,
                             const float* __restrict__ tok,
                             const float* __restrict__ pos,
                             float* __restrict__ x)
{
    int row = blockIdx.x;
    int s = row % S_;
    long long id = ids[row];
    float* xr = x + (long long)row * E_;
    const float* tr = tok + id * E_;
    const float* pr = pos + (long long)s * E_;
    for (int i = threadIdx.x; i < E_; i += blockDim.x)
        xr[i] = tr[i] + pr[i];
}

// LayerNorm over last dim E (one block per row, 128 threads)
__global__ void ln_kernel(const float* __restrict__ x,
                          const float* __restrict__ g,
                          const float* __restrict__ b,
                          float* __restrict__ y)
{
    int row = blockIdx.x;
    const float* xr = x + (long long)row * E_;
    float s = 0.f, ss = 0.f;
    for (int i = threadIdx.x; i < E_; i += 128) {
        float v = xr[i];
        s += v; ss += v * v;
    }
#pragma unroll
    for (int o = 16; o > 0; o >>= 1) {
        s  += __shfl_xor_sync(0xffffffffu, s, o);
        ss += __shfl_xor_sync(0xffffffffu, ss, o);
    }
    __shared__ float sh_s[4], sh_ss[4];
    int w = threadIdx.x >> 5;
    if ((threadIdx.x & 31) == 0) { sh_s[w] = s; sh_ss[w] = ss; }
    __syncthreads();
    s  = sh_s[0] + sh_s[1] + sh_s[2] + sh_s[3];
    ss = sh_ss[0] + sh_ss[1] + sh_ss[2] + sh_ss[3];
    float mean = s / E_;
    float var  = ss / E_ - mean * mean;
    float rstd = rsqrtf(var + EPS_);
    float* yr = y + (long long)row * E_;
    for (int i = threadIdx.x; i < E_; i += 128)
        yr[i] = (xr[i] - mean) * rstd * g[i] + b[i];
}

// causal softmax over rows of the [H*B, S, S] score matrix (one warp per row)
__global__ void softmax_causal(float* __restrict__ attn)
{
    int row = blockIdx.x * 8 + threadIdx.y;
    int lane = threadIdx.x;
    int qi = row % S_;
    float* p = attn + (long long)row * S_;
    int n = qi + 1;
    float mx = -1e30f;
    for (int j = lane; j < n; j += 32) mx = fmaxf(mx, p[j]);
#pragma unroll
    for (int o = 16; o > 0; o >>= 1) mx = fmaxf(mx, __shfl_xor_sync(0xffffffffu, mx, o));
    float sum = 0.f;
    for (int j = lane; j < n; j += 32) {
        float e = expf(p[j] - mx);
        p[j] = e;
        sum += e;
    }
#pragma unroll
    for (int o = 16; o > 0; o >>= 1) sum += __shfl_xor_sync(0xffffffffu, sum, o);
    float inv = 1.f / sum;
    for (int j = lane; j < n; j += 32) p[j] *= inv;
    for (int j = n + lane; j < S_; j += 32) p[j] = 0.f;
}

// o_cat[(b*S+s), h*D+d] = o_head[h, (b*S+s), d]
__global__ void concat_heads(const float* __restrict__ oh, float* __restrict__ oc)
{
    int idx = blockIdx.x * blockDim.x + threadIdx.x;
    if (idx >= BS_ * HD_) return;
    int row = idx / HD_;
    int c = idx % HD_;
    int h = c / D_, d = c % D_;
    oc[idx] = oh[((long long)h * BS_ + row) * D_ + d];
}

// per-row cross-entropy: acc += logits[row, tgt[row]] - logsumexp(logits[row, :])
__global__ void loss_kernel(const float* __restrict__ logits,
                            const int* __restrict__ tgt,
                            float* __restrict__ acc)
{
    int row = blockIdx.x;
    const float* p = logits + (long long)row * V_;
    __shared__ float sh[8];
    float mx = -1e30f;
    for (int j = threadIdx.x; j < V_; j += 256) mx = fmaxf(mx, p[j]);
#pragma unroll
    for (int o = 16; o > 0; o >>= 1) mx = fmaxf(mx, __shfl_xor_sync(0xffffffffu, mx, o));
    int w = threadIdx.x >> 5;
    if ((threadIdx.x & 31) == 0) sh[w] = mx;
    __syncthreads();
    mx = sh[0];
#pragma unroll
    for (int i = 1; i < 8; i++) mx = fmaxf(mx, sh[i]);
    __syncthreads();
    float sum = 0.f;
    for (int j = threadIdx.x; j < V_; j += 256) sum += expf(p[j] - mx);
#pragma unroll
    for (int o = 16; o > 0; o >>= 1) sum += __shfl_xor_sync(0xffffffffu, sum, o);
    if ((threadIdx.x & 31) == 0) sh[w] = sum;
    __syncthreads();
    if (threadIdx.x == 0) {
        float tot = 0.f;
#pragma unroll
        for (int i = 0; i < 8; i++) tot += sh[i];
        float lse = mx + logf(tot);
        atomicAdd(acc, p[tgt[row]] - lse);
    }
}

__global__ void zero_loss(float* a) { *a = 0.f; }
__global__ void fin_loss(const float* a, float* out) { *out = -(*a) / (float)BS_; }

// ---------------- host driver ----------------
static void launch_sgemm(const float* A, const float* Bm, const float* bias, float* C,
                         int M, int N, int K, int lda, int ldb, int ldc,
                         long long sA, long long sB, long long sBias, long long sC,
                         int batch, float alpha, int flags)
{
    dim3 grid((N + 63) / 64, (M + 63) / 64, batch);
    sgemm_kernel<<<grid, 256>>>(A, Bm, bias, C, M, N, K, lda, ldb, ldc,
                                sA, sB, sBias, sC, alpha, flags);
}

extern "C" void kernel_launch(void* const* d_in, const int* in_sizes, int n_in,
                              void* d_out, int out_size)
{
    const int*   input_ids = (const int*)d_in[0];
    const int*   targets   = (const int*)d_in[1];
    const float* tok_emb   = (const float*)d_in[2];
    const float* pos_emb   = (const float*)d_in[3];
    const float* Wq  = (const float*)d_in[4];
    const float* bq  = (const float*)d_in[5];
    const float* Wk  = (const float*)d_in[6];
    const float* bk  = (const float*)d_in[7];
    const float* Wv  = (const float*)d_in[8];
    const float* bv  = (const float*)d_in[9];
    const float* Wc  = (const float*)d_in[10];
    const float* bc  = (const float*)d_in[11];
    const float* g1  = (const float*)d_in[12];
    const float* b1  = (const float*)d_in[13];
    const float* g2  = (const float*)d_in[14];
    const float* b2  = (const float*)d_in[15];
    const float* W1  = (const float*)d_in[16];
    const float* bf1 = (const float*)d_in[17];
    const float* W2  = (const float*)d_in[18];
    const float* bf2 = (const float*)d_in[19];
    const float* gf   = (const float*)d_in[20];
    const float* bfin = (const float*)d_in[21];
    const float* Wout = (const float*)d_in[22];
    const float* bout = (const float*)d_in[23];
    float* out = (float*)d_out;

    float *x, *xn, *q, *k, *v, *attn, *ocat, *hbuf, *lossp;
    cudaGetSymbolAddress((void**)&x,    g_x);
    cudaGetSymbolAddress((void**)&xn,   g_xn);
    cudaGetSymbolAddress((void**)&q,    g_q);
    cudaGetSymbolAddress((void**)&k,    g_k);
    cudaGetSymbolAddress((void**)&v,    g_v);
    cudaGetSymbolAddress((void**)&attn, g_attn);
    cudaGetSymbolAddress((void**)&ocat, g_ocat);
    cudaGetSymbolAddress((void**)&hbuf, g_h);
    cudaGetSymbolAddress((void**)&lossp, g_loss);

    const float scale = 1.0f / sqrtf((float)D_);

    // 1. embedding
    embed_kernel<<<BS_, 128>>>(input_ids, tok_emb, pos_emb, x);

    for (int l = 0; l < L_; l++) {
        const long long wqoff = (long long)l * H_ * E_ * D_;
        // ln1
        ln_kernel<<<BS_, 128>>>(x, g1 + l * E_, b1 + l * E_, xn);
        // q/k/v projections (batched over heads), stored [H, B*S, D]
        launch_sgemm(xn, Wq + wqoff, bq + (long long)l * H_ * D_, q,
                     BS_, D_, E_, E_, D_, D_,
                     0, (long long)E_ * D_, D_, (long long)BS_ * D_,
                     H_, 1.f, 0);
        launch_sgemm(xn, Wk + wqoff, bk + (long long)l * H_ * D_, k,
                     BS_, D_, E_, E_, D_, D_,
                     0, (long long)E_ * D_, D_, (long long)BS_ * D_,
                     H_, 1.f, 0);
        launch_sgemm(xn, Wv + wqoff, bv + (long long)l * H_ * D_, v,
                     BS_, D_, E_, E_, D_, D_,
                     0, (long long)E_ * D_, D_, (long long)BS_ * D_,
                     H_, 1.f, 0);
        // scores: attn[z] = q[z] @ k[z]^T * scale, z over (h,b) = H*B batches
        launch_sgemm(q, k, nullptr, attn,
                     S_, S_, D_, D_, D_, S_,
                     (long long)S_ * D_, (long long)S_ * D_, 0, (long long)S_ * S_,
                     H_ * B_, scale, FLAG_TRANSB);
        // causal softmax (one warp per row)
        {
            dim3 blk(32, 8);
            softmax_causal<<<(H_ * B_ * S_) / 8, blk>>>(attn);
        }
        // o_head = attn @ v  (reuse q buffer as output)
        launch_sgemm(attn, v, nullptr, q,
                     S_, D_, S_, S_, D_, D_,
                     (long long)S_ * S_, (long long)S_ * D_, 0, (long long)S_ * D_,
                     H_ * B_, 1.f, 0);
        // concat heads
        concat_heads<<<(BS_ * HD_ + 255) / 256, 256>>>(q, ocat);
        // x += ocat @ Wc[l] + bc[l]
        launch_sgemm(ocat, Wc + (long long)l * HD_ * E_, bc + l * E_, x,
                     BS_, E_, HD_, HD_, E_, E_,
                     0, 0, 0, 0, 1, 1.f, FLAG_ACC);
        // ln2
        ln_kernel<<<BS_, 128>>>(x, g2 + l * E_, b2 + l * E_, xn);
        // h = gelu(xn @ W1[l] + bf1[l])
        launch_sgemm(xn, W1 + (long long)l * E_ * FF_, bf1 + (long long)l * FF_, hbuf,
                     BS_, FF_, E_, E_, FF_, FF_,
                     0, 0, 0, 0, 1, 1.f, FLAG_GELU);
        // x += h @ W2[l] + bf2[l]
        launch_sgemm(hbuf, W2 + (long long)l * FF_ * E_, bf2 + l * E_, x,
                     BS_, E_, FF_, FF_, E_, E_,
                     0, 0, 0, 0, 1, 1.f, FLAG_ACC);
    }

    // final LN + logits
    ln_kernel<<<BS_, 128>>>(x, gf, bfin, xn);
    launch_sgemm(xn, Wout, bout, out,
                 BS_, V_, E_, E_, V_, V_,
                 0, 0, 0, 0, 1, 1.f, 0);

    // loss (if the output buffer includes the scalar slot)
    const long long NLOG = (long long)BS_ * V_;
    if ((long long)out_size > NLOG) {
        zero_loss<<<1, 1>>>(lossp);
        loss_kernel<<<BS_, 256>>>(out, targets, lossp);
        fin_loss<<<1, 1>>>(lossp, out + NLOG);
    }
}

// round 2
// speedup vs baseline: 1.9542x; 1.9542x over previous
#include <cuda_runtime.h>
#include <math.h>
#include <stdint.h>

// ---------------- problem constants ----------------
constexpr int B_  = 8;
constexpr int S_  = 512;
constexpr int E_  = 384;
constexpr int H_  = 7;
constexpr int D_  = 54;
constexpr int L_  = 7;
constexpr int V_  = 32000;
constexpr int FF_ = 6 * E_;          // 2304
constexpr int BS_ = B_ * S_;         // 4096
constexpr int HD_ = H_ * D_;         // 378
constexpr float EPS_ = 1e-5f;

// ---------------- scratch (static device memory; no allocation) ----------------
__device__ float g_x   [BS_ * E_];
__device__ float g_xn  [BS_ * E_];
__device__ float g_q   [H_ * BS_ * D_];
__device__ float g_k   [H_ * BS_ * D_];
__device__ float g_v   [H_ * BS_ * D_];
__device__ float g_attn[(size_t)H_ * B_ * S_ * S_];
__device__ float g_ocat[BS_ * HD_];
__device__ float g_h   [BS_ * FF_];
__device__ float g_loss;

#define FLAG_TRANSB 1
#define FLAG_ACC    2
#define FLAG_GELU   4

__device__ __forceinline__ float gelu_f(float x) {
    return 0.5f * x * (1.0f + erff(x * 0.70710678118654752f));
}

__device__ __forceinline__ uint32_t f2tf32(float x) {
    uint32_t r;
    asm("cvt.rna.tf32.f32 %0, %1;" : "=r"(r) : "f"(x));
    return r;
}

// ---------------- tf32 tensor-core GEMM ----------------
// C = alpha * A @ B (+bias) (+C), optional GELU. Same interface as the fp32 path.
// Tile: 128x64x16, 8 warps (4x2), warp tile 32x32 = 2x4 mma.m16n8k8 fragments.
constexpr int BM = 128, BN = 64, BK = 16;
constexpr int ASTR = BM + 4;   // padded k-major A stride (conflict-free frags)
constexpr int BSTR = BN + 4;

__global__ void __launch_bounds__(256, 2)
tgemm_kernel(const float* __restrict__ A, const float* __restrict__ Bm,
             const float* __restrict__ bias, float* __restrict__ C,
             int M, int N, int K, int lda, int ldb, int ldc,
             long long sA, long long sB, long long sBias, long long sC,
             float alpha, int flags)
{
    __shared__ uint32_t As[2][BK * ASTR];
    __shared__ uint32_t Bs[2][BK * BSTR];

    const int z = blockIdx.z;
    A  += (long long)z * sA;
    Bm += (long long)z * sB;
    C  += (long long)z * sC;
    if (bias) bias += (long long)z * sBias;

    const int row0 = blockIdx.y * BM;
    const int col0 = blockIdx.x * BN;
    const int tid  = threadIdx.x;
    const int warp = tid >> 5;
    const int lane = tid & 31;
    const int wm = (warp >> 1) * 32;   // warp m-origin within block
    const int wn = (warp & 1) * 32;    // warp n-origin within block
    const int lr = lane >> 2;          // 0..7
    const int lc = lane & 3;           // 0..3
    const bool transB = (flags & FLAG_TRANSB);

    float acc[2][4][4];
#pragma unroll
    for (int mt = 0; mt < 2; mt++)
#pragma unroll
        for (int nt = 0; nt < 4; nt++)
#pragma unroll
            for (int c = 0; c < 4; c++) acc[mt][nt][c] = 0.f;

    float aR[8], bR[4];
    const int nk = (K + BK - 1) / BK;

    // ---- tile loaders (LDG into registers) ----
#define LDG_TILE(K0)                                                          \
    {                                                                         \
        _Pragma("unroll")                                                     \
        for (int i = 0; i < 8; i++) {                                         \
            int e = tid + i * 256;                                            \
            int m = e >> 4, k = e & 15;                                       \
            int gr = row0 + m, gc = (K0) + k;                                 \
            aR[i] = (gr < M && gc < K) ? A[(long long)gr * lda + gc] : 0.f;   \
        }                                                                     \
        if (transB) {                                                         \
            _Pragma("unroll")                                                 \
            for (int i = 0; i < 4; i++) {                                     \
                int e = tid + i * 256;                                        \
                int n = e >> 4, k = e & 15;                                   \
                int gn = col0 + n, gc = (K0) + k;                             \
                bR[i] = (gn < N && gc < K) ? Bm[(long long)gn * ldb + gc] : 0.f; \
            }                                                                 \
        } else {                                                              \
            _Pragma("unroll")                                                 \
            for (int i = 0; i < 4; i++) {                                     \
                int e = tid + i * 256;                                        \
                int k = e >> 6, n = e & 63;                                   \
                int gc = (K0) + k, gn = col0 + n;                             \
                bR[i] = (gc < K && gn < N) ? Bm[(long long)gc * ldb + gn] : 0.f; \
            }                                                                 \
        }                                                                     \
    }

#define STS_TILE(BUF)                                                         \
    {                                                                         \
        _Pragma("unroll")                                                     \
        for (int i = 0; i < 8; i++) {                                         \
            int e = tid + i * 256;                                            \
            int m = e >> 4, k = e & 15;                                       \
            As[BUF][k * ASTR + m] = f2tf32(aR[i]);                            \
        }                                                                     \
        if (transB) {                                                         \
            _Pragma("unroll")                                                 \
            for (int i = 0; i < 4; i++) {                                     \
                int e = tid + i * 256;                                        \
                int n = e >> 4, k = e & 15;                                   \
                Bs[BUF][k * BSTR + n] = f2tf32(bR[i]);                        \
            }                                                                 \
        } else {                                                              \
            _Pragma("unroll")                                                 \
            for (int i = 0; i < 4; i++) {                                     \
                int e = tid + i * 256;                                        \
                int k = e >> 6, n = e & 63;                                   \
                Bs[BUF][k * BSTR + n] = f2tf32(bR[i]);                        \
            }                                                                 \
        }                                                                     \
    }

    LDG_TILE(0)
    STS_TILE(0)
    __syncthreads();

    int buf = 0;
    for (int it = 0; it < nk; it++) {
        if (it + 1 < nk) LDG_TILE((it + 1) * BK)

        // compute from As[buf]/Bs[buf]: 2 k-steps of 8
#pragma unroll
        for (int ks = 0; ks < 2; ks++) {
            const int kk = ks * 8;
            uint32_t af[2][4], bf[4][2];
#pragma unroll
            for (int mt = 0; mt < 2; mt++) {
                int m0 = wm + mt * 16 + lr;
                af[mt][0] = As[buf][(kk + lc) * ASTR + m0];
                af[mt][1] = As[buf][(kk + lc) * ASTR + m0 + 8];
                af[mt][2] = As[buf][(kk + lc + 4) * ASTR + m0];
                af[mt][3] = As[buf][(kk + lc + 4) * ASTR + m0 + 8];
            }
#pragma unroll
            for (int nt = 0; nt < 4; nt++) {
                int n0 = wn + nt * 8 + lr;
                bf[nt][0] = Bs[buf][(kk + lc) * BSTR + n0];
                bf[nt][1] = Bs[buf][(kk + lc + 4) * BSTR + n0];
            }
#pragma unroll
            for (int mt = 0; mt < 2; mt++)
#pragma unroll
                for (int nt = 0; nt < 4; nt++) {
                    asm volatile(
                        "mma.sync.aligned.m16n8k8.row.col.f32.tf32.tf32.f32 "
                        "{%0,%1,%2,%3}, {%4,%5,%6,%7}, {%8,%9}, {%0,%1,%2,%3};"
                        : "+f"(acc[mt][nt][0]), "+f"(acc[mt][nt][1]),
                          "+f"(acc[mt][nt][2]), "+f"(acc[mt][nt][3])
                        : "r"(af[mt][0]), "r"(af[mt][1]),
                          "r"(af[mt][2]), "r"(af[mt][3]),
                          "r"(bf[nt][0]), "r"(bf[nt][1]));
                }
        }

        if (it + 1 < nk) {
            STS_TILE(buf ^ 1)
            __syncthreads();
            buf ^= 1;
        }
    }

    // ---- epilogue ----
#pragma unroll
    for (int mt = 0; mt < 2; mt++)
#pragma unroll
        for (int nt = 0; nt < 4; nt++) {
            int rb = row0 + wm + mt * 16 + lr;
            int cb = col0 + wn + nt * 8 + lc * 2;
#pragma unroll
            for (int h = 0; h < 2; h++) {
                int r = rb + h * 8;
                if (r >= M) continue;
#pragma unroll
                for (int j = 0; j < 2; j++) {
                    int c = cb + j;
                    if (c >= N) continue;
                    float vv = acc[mt][nt][h * 2 + j] * alpha;
                    if (bias) vv += bias[c];
                    if (flags & FLAG_GELU) vv = gelu_f(vv);
                    long long ci = (long long)r * ldc + c;
                    if (flags & FLAG_ACC) vv += C[ci];
                    C[ci] = vv;
                }
            }
        }
#undef LDG_TILE
#undef STS_TILE
}

// ---------------- pointwise / reduction kernels (unchanged) ----------------
__global__ void embed_kernel(const int* __restrict__ ids,
                             const float* __restrict__ tok,
                             const float* __restrict__ pos,
                             float* __restrict__ x)
{
    int row = blockIdx.x;
    int s = row % S_;
    long long id = ids[row];
    float* xr = x + (long long)row * E_;
    const float* tr = tok + id * E_;
    const float* pr = pos + (long long)s * E_;
    for (int i = threadIdx.x; i < E_; i += blockDim.x)
        xr[i] = tr[i] + pr[i];
}

__global__ void ln_kernel(const float* __restrict__ x,
                          const float* __restrict__ g,
                          const float* __restrict__ b,
                          float* __restrict__ y)
{
    int row = blockIdx.x;
    const float* xr = x + (long long)row * E_;
    float s = 0.f, ss = 0.f;
    for (int i = threadIdx.x; i < E_; i += 128) {
        float v = xr[i];
        s += v; ss += v * v;
    }
#pragma unroll
    for (int o = 16; o > 0; o >>= 1) {
        s  += __shfl_xor_sync(0xffffffffu, s, o);
        ss += __shfl_xor_sync(0xffffffffu, ss, o);
    }
    __shared__ float sh_s[4], sh_ss[4];
    int w = threadIdx.x >> 5;
    if ((threadIdx.x & 31) == 0) { sh_s[w] = s; sh_ss[w] = ss; }
    __syncthreads();
    s  = sh_s[0] + sh_s[1] + sh_s[2] + sh_s[3];
    ss = sh_ss[0] + sh_ss[1] + sh_ss[2] + sh_ss[3];
    float mean = s / E_;
    float var  = ss / E_ - mean * mean;
    float rstd = rsqrtf(var + EPS_);
    float* yr = y + (long long)row * E_;
    for (int i = threadIdx.x; i < E_; i += 128)
        yr[i] = (xr[i] - mean) * rstd * g[i] + b[i];
}

__global__ void softmax_causal(float* __restrict__ attn)
{
    int row = blockIdx.x * 8 + threadIdx.y;
    int lane = threadIdx.x;
    int qi = row % S_;
    float* p = attn + (long long)row * S_;
    int n = qi + 1;
    float mx = -1e30f;
    for (int j = lane; j < n; j += 32) mx = fmaxf(mx, p[j]);
#pragma unroll
    for (int o = 16; o > 0; o >>= 1) mx = fmaxf(mx, __shfl_xor_sync(0xffffffffu, mx, o));
    float sum = 0.f;
    for (int j = lane; j < n; j += 32) {
        float e = expf(p[j] - mx);
        p[j] = e;
        sum += e;
    }
#pragma unroll
    for (int o = 16; o > 0; o >>= 1) sum += __shfl_xor_sync(0xffffffffu, sum, o);
    float inv = 1.f / sum;
    for (int j = lane; j < n; j += 32) p[j] *= inv;
    for (int j = n + lane; j < S_; j += 32) p[j] = 0.f;
}

__global__ void concat_heads(const float* __restrict__ oh, float* __restrict__ oc)
{
    int idx = blockIdx.x * blockDim.x + threadIdx.x;
    if (idx >= BS_ * HD_) return;
    int row = idx / HD_;
    int c = idx % HD_;
    int h = c / D_, d = c % D_;
    oc[idx] = oh[((long long)h * BS_ + row) * D_ + d];
}

__global__ void loss_kernel(const float* __restrict__ logits,
                            const int* __restrict__ tgt,
                            float* __restrict__ acc)
{
    int row = blockIdx.x;
    const float* p = logits + (long long)row * V_;
    __shared__ float sh[8];
    float mx = -1e30f;
    for (int j = threadIdx.x; j < V_; j += 256) mx = fmaxf(mx, p[j]);
#pragma unroll
    for (int o = 16; o > 0; o >>= 1) mx = fmaxf(mx, __shfl_xor_sync(0xffffffffu, mx, o));
    int w = threadIdx.x >> 5;
    if ((threadIdx.x & 31) == 0) sh[w] = mx;
    __syncthreads();
    mx = sh[0];
#pragma unroll
    for (int i = 1; i < 8; i++) mx = fmaxf(mx, sh[i]);
    __syncthreads();
    float sum = 0.f;
    for (int j = threadIdx.x; j < V_; j += 256) sum += expf(p[j] - mx);
#pragma unroll
    for (int o = 16; o > 0; o >>= 1) sum += __shfl_xor_sync(0xffffffffu, sum, o);
    if ((threadIdx.x & 31) == 0) sh[w] = sum;
    __syncthreads();
    if (threadIdx.x == 0) {
        float tot = 0.f;
#pragma unroll
        for (int i = 0; i < 8; i++) tot += sh[i];
        float lse = mx + logf(tot);
        atomicAdd(acc, p[tgt[row]] - lse);
    }
}

__global__ void zero_loss(float* a) { *a = 0.f; }
__global__ void fin_loss(const float* a, float* out) { *out = -(*a) / (float)BS_; }

// ---------------- host driver ----------------
static void launch_gemm(const float* A, const float* Bm, const float* bias, float* C,
                        int M, int N, int K, int lda, int ldb, int ldc,
                        long long sA, long long sB, long long sBias, long long sC,
                        int batch, float alpha, int flags)
{
    dim3 grid((N + BN - 1) / BN, (M + BM - 1) / BM, batch);
    tgemm_kernel<<<grid, 256>>>(A, Bm, bias, C, M, N, K, lda, ldb, ldc,
                                sA, sB, sBias, sC, alpha, flags);
}

extern "C" void kernel_launch(void* const* d_in, const int* in_sizes, int n_in,
                              void* d_out, int out_size)
{
    const int*   input_ids = (const int*)d_in[0];
    const int*   targets   = (const int*)d_in[1];
    const float* tok_emb   = (const float*)d_in[2];
    const float* pos_emb   = (const float*)d_in[3];
    const float* Wq  = (const float*)d_in[4];
    const float* bq  = (const float*)d_in[5];
    const float* Wk  = (const float*)d_in[6];
    const float* bk  = (const float*)d_in[7];
    const float* Wv  = (const float*)d_in[8];
    const float* bv  = (const float*)d_in[9];
    const float* Wc  = (const float*)d_in[10];
    const float* bc  = (const float*)d_in[11];
    const float* g1  = (const float*)d_in[12];
    const float* b1  = (const float*)d_in[13];
    const float* g2  = (const float*)d_in[14];
    const float* b2  = (const float*)d_in[15];
    const float* W1  = (const float*)d_in[16];
    const float* bf1 = (const float*)d_in[17];
    const float* W2  = (const float*)d_in[18];
    const float* bf2 = (const float*)d_in[19];
    const float* gf   = (const float*)d_in[20];
    const float* bfin = (const float*)d_in[21];
    const float* Wout = (const float*)d_in[22];
    const float* bout = (const float*)d_in[23];
    float* out = (float*)d_out;

    float *x, *xn, *q, *k, *v, *attn, *ocat, *hbuf, *lossp;
    cudaGetSymbolAddress((void**)&x,    g_x);
    cudaGetSymbolAddress((void**)&xn,   g_xn);
    cudaGetSymbolAddress((void**)&q,    g_q);
    cudaGetSymbolAddress((void**)&k,    g_k);
    cudaGetSymbolAddress((void**)&v,    g_v);
    cudaGetSymbolAddress((void**)&attn, g_attn);
    cudaGetSymbolAddress((void**)&ocat, g_ocat);
    cudaGetSymbolAddress((void**)&hbuf, g_h);
    cudaGetSymbolAddress((void**)&lossp, g_loss);

    const float scale = 1.0f / sqrtf((float)D_);

    embed_kernel<<<BS_, 128>>>(input_ids, tok_emb, pos_emb, x);

    for (int l = 0; l < L_; l++) {
        const long long wqoff = (long long)l * H_ * E_ * D_;
        ln_kernel<<<BS_, 128>>>(x, g1 + l * E_, b1 + l * E_, xn);
        launch_gemm(xn, Wq + wqoff, bq + (long long)l * H_ * D_, q,
                    BS_, D_, E_, E_, D_, D_,
                    0, (long long)E_ * D_, D_, (long long)BS_ * D_,
                    H_, 1.f, 0);
        launch_gemm(xn, Wk + wqoff, bk + (long long)l * H_ * D_, k,
                    BS_, D_, E_, E_, D_, D_,
                    0, (long long)E_ * D_, D_, (long long)BS_ * D_,
                    H_, 1.f, 0);
        launch_gemm(xn, Wv + wqoff, bv + (long long)l * H_ * D_, v,
                    BS_, D_, E_, E_, D_, D_,
                    0, (long long)E_ * D_, D_, (long long)BS_ * D_,
                    H_, 1.f, 0);
        launch_gemm(q, k, nullptr, attn,
                    S_, S_, D_, D_, D_, S_,
                    (long long)S_ * D_, (long long)S_ * D_, 0, (long long)S_ * S_,
                    H_ * B_, scale, FLAG_TRANSB);
        {
            dim3 blk(32, 8);
            softmax_causal<<<(H_ * B_ * S_) / 8, blk>>>(attn);
        }
        launch_gemm(attn, v, nullptr, q,
                    S_, D_, S_, S_, D_, D_,
                    (long long)S_ * S_, (long long)S_ * D_, 0, (long long)S_ * D_,
                    H_ * B_, 1.f, 0);
        concat_heads<<<(BS_ * HD_ + 255) / 256, 256>>>(q, ocat);
        launch_gemm(ocat, Wc + (long long)l * HD_ * E_, bc + l * E_, x,
                    BS_, E_, HD_, HD_, E_, E_,
                    0, 0, 0, 0, 1, 1.f, FLAG_ACC);
        ln_kernel<<<BS_, 128>>>(x, g2 + l * E_, b2 + l * E_, xn);
        launch_gemm(xn, W1 + (long long)l * E_ * FF_, bf1 + (long long)l * FF_, hbuf,
                    BS_, FF_, E_, E_, FF_, FF_,
                    0, 0, 0, 0, 1, 1.f, FLAG_GELU);
        launch_gemm(hbuf, W2 + (long long)l * FF_ * E_, bf2 + l * E_, x,
                    BS_, E_, FF_, FF_, E_, E_,
                    0, 0, 0, 0, 1, 1.f, FLAG_ACC);
    }

    ln_kernel<<<BS_, 128>>>(x, gf, bfin, xn);
    launch_gemm(xn, Wout, bout, out,
                BS_, V_, E_, E_, V_, V_,
                0, 0, 0, 0, 1, 1.f, 0);

    const long long NLOG = (long long)BS_ * V_;
    if ((long long)out_size > NLOG) {
        zero_loss<<<1, 1>>>(lossp);
        loss_kernel<<<BS_, 256>>>(out, targets, lossp);
        fin_loss<<<1, 1>>>(lossp, out + NLOG);
    }
}

// round 3
// speedup vs baseline: 2.2438x; 1.1482x over previous
#include <cuda_runtime.h>
#include <math.h>
#include <stdint.h>

// ---------------- problem constants ----------------
constexpr int B_  = 8;
constexpr int S_  = 512;
constexpr int E_  = 384;
constexpr int H_  = 7;
constexpr int D_  = 54;
constexpr int L_  = 7;
constexpr int V_  = 32000;
constexpr int FF_ = 6 * E_;          // 2304
constexpr int BS_ = B_ * S_;         // 4096
constexpr int HD_ = H_ * D_;         // 378
constexpr int HB_ = 192;             // padded head block: q(64)|k(64)|v(64)
constexpr int QLD_ = H_ * HB_;       // 1344, qkv row width
constexpr float EPS_ = 1e-5f;

// ---------------- scratch (static device memory; no allocation) ----------------
__device__ float g_x   [BS_ * E_];
__device__ float g_xn  [BS_ * E_];
__device__ float g_qkv [BS_ * QLD_];                 // fused padded qkv
__device__ float g_wqkv[L_ * E_ * QLD_];             // repacked qkv weights
__device__ float g_bqkv[L_ * QLD_];
__device__ float g_attn[(size_t)B_ * H_ * S_ * S_];  // [b,h,s,s]
__device__ float g_ocat[BS_ * HD_];
__device__ float g_h   [BS_ * FF_];
__device__ float g_loss;

#define FLAG_TRANSB 1
#define FLAG_ACC    2
#define FLAG_GELU   4

__device__ __forceinline__ float gelu_f(float x) {
    return 0.5f * x * (1.0f + erff(x * 0.70710678118654752f));
}
__device__ __forceinline__ uint32_t f2tf32(float x) {
    uint32_t r;
    asm("cvt.rna.tf32.f32 %0, %1;" : "=r"(r) : "f"(x));
    return r;
}

// =====================================================================
// tf32 tensor-core GEMM, templated tile width.
// BM=128 fixed (all M here are multiples of 128, grid.y = M/128 exact).
// BN=128: 8 warps 4x2, warp tile 32x64 (NT=8).  BN=64: warp tile 32x32 (NT=4).
// Batched via z -> (z/zdiv, z%zdiv) with two strides per operand.
// =====================================================================
template<int BN, int NT>
__global__ void __launch_bounds__(256, (BN == 64 ? 2 : 1))
tc_gemm(const float* __restrict__ A, const float* __restrict__ Bm,
        const float* __restrict__ bias, float* __restrict__ C,
        int M, int N, int Nb, int K,
        int lda, int ldb, int ldc, int zdiv,
        long long sA1, long long sA2, long long sB1, long long sB2,
        long long sC1, long long sC2,
        float alpha, int flags)
{
    constexpr int BM = 128, BK = 16;
    constexpr int ASTR = BM + 4;
    constexpr int BSTR = BN + 4;
    constexpr int BEL  = BN * BK / 256;   // B staging elems per thread (8 or 4)

    __shared__ uint32_t As[2][BK * ASTR];
    __shared__ uint32_t Bs[2][BK * BSTR];

    {
        const int z = blockIdx.z;
        const int zq = z / zdiv, zr = z - zq * zdiv;
        A  += (long long)zq * sA1 + (long long)zr * sA2;
        Bm += (long long)zq * sB1 + (long long)zr * sB2;
        C  += (long long)zq * sC1 + (long long)zr * sC2;
    }

    const int row0 = blockIdx.y * BM;
    const int col0 = blockIdx.x * BN;
    const int tid  = threadIdx.x;
    const int warp = tid >> 5;
    const int lane = tid & 31;
    const int wm = (warp >> 1) * 32;
    const int wn = (warp & 1) * (BN / 2);
    const int lr = lane >> 2;
    const int lc = lane & 3;
    const bool transB = (flags & FLAG_TRANSB);
    const bool a4 = ((lda & 3) == 0);
    const bool a2 = ((lda & 1) == 0);
    const bool b4 = ((ldb & 3) == 0);
    const bool nfull = (col0 + BN <= Nb);

    float acc[2][NT][4];
#pragma unroll
    for (int mt = 0; mt < 2; mt++)
#pragma unroll
        for (int nt = 0; nt < NT; nt++)
#pragma unroll
            for (int c = 0; c < 4; c++) acc[mt][nt][c] = 0.f;

    float aR[8], bR[BEL];
    const int nk = (K + BK - 1) / BK;

    auto loadA = [&](int k0, bool kfull) {
        if (kfull && a4) {
#pragma unroll
            for (int i = 0; i < 2; i++) {
                int e = tid + i * 256;
                int m = e >> 2, k4 = (e & 3) << 2;
                float4 v = *reinterpret_cast<const float4*>(
                    A + (long long)(row0 + m) * lda + k0 + k4);
                aR[i*4+0] = v.x; aR[i*4+1] = v.y; aR[i*4+2] = v.z; aR[i*4+3] = v.w;
            }
        } else if (kfull && a2) {
#pragma unroll
            for (int i = 0; i < 4; i++) {
                int e = tid + i * 256;
                int m = e >> 3, k2 = (e & 7) << 1;
                float2 v = *reinterpret_cast<const float2*>(
                    A + (long long)(row0 + m) * lda + k0 + k2);
                aR[i*2+0] = v.x; aR[i*2+1] = v.y;
            }
        } else {
#pragma unroll
            for (int i = 0; i < 8; i++) {
                int e = tid + i * 256;
                int m = e >> 4, k = e & 15;
                aR[i] = (k0 + k < K) ? A[(long long)(row0 + m) * lda + k0 + k] : 0.f;
            }
        }
    };
    auto stsA = [&](bool kfull, int buf) {
        if (kfull && a4) {
#pragma unroll
            for (int i = 0; i < 2; i++) {
                int e = tid + i * 256;
                int m = e >> 2, k4 = (e & 3) << 2;
#pragma unroll
                for (int j = 0; j < 4; j++)
                    As[buf][(k4 + j) * ASTR + m] = f2tf32(aR[i*4+j]);
            }
        } else if (kfull && a2) {
#pragma unroll
            for (int i = 0; i < 4; i++) {
                int e = tid + i * 256;
                int m = e >> 3, k2 = (e & 7) << 1;
                As[buf][(k2 + 0) * ASTR + m] = f2tf32(aR[i*2+0]);
                As[buf][(k2 + 1) * ASTR + m] = f2tf32(aR[i*2+1]);
            }
        } else {
#pragma unroll
            for (int i = 0; i < 8; i++) {
                int e = tid + i * 256;
                int m = e >> 4, k = e & 15;
                As[buf][k * ASTR + m] = f2tf32(aR[i]);
            }
        }
    };
    auto loadB = [&](int k0, bool kfull) {
        const bool fast = kfull && nfull && b4;
        if (transB) {
            if (fast) {
#pragma unroll
                for (int i = 0; i < BEL / 4; i++) {
                    int e = tid + i * 256;
                    int n = e >> 2, k4 = (e & 3) << 2;
                    float4 v = *reinterpret_cast<const float4*>(
                        Bm + (long long)(col0 + n) * ldb + k0 + k4);
                    bR[i*4+0] = v.x; bR[i*4+1] = v.y; bR[i*4+2] = v.z; bR[i*4+3] = v.w;
                }
            } else {
#pragma unroll
                for (int i = 0; i < BEL; i++) {
                    int e = tid + i * 256;
                    int n = e >> 4, k = e & 15;
                    bR[i] = (col0 + n < Nb && k0 + k < K)
                          ? Bm[(long long)(col0 + n) * ldb + k0 + k] : 0.f;
                }
            }
        } else {
            if (fast) {
#pragma unroll
                for (int i = 0; i < BEL / 4; i++) {
                    int e = tid + i * 256;
                    int k = e / (BN / 4), n4 = (e % (BN / 4)) << 2;
                    float4 v = *reinterpret_cast<const float4*>(
                        Bm + (long long)(k0 + k) * ldb + col0 + n4);
                    bR[i*4+0] = v.x; bR[i*4+1] = v.y; bR[i*4+2] = v.z; bR[i*4+3] = v.w;
                }
            } else {
#pragma unroll
                for (int i = 0; i < BEL; i++) {
                    int e = tid + i * 256;
                    int k = e / BN, n = e % BN;
                    bR[i] = (k0 + k < K && col0 + n < Nb)
                          ? Bm[(long long)(k0 + k) * ldb + col0 + n] : 0.f;
                }
            }
        }
    };
    auto stsB = [&](bool kfull, int buf) {
        const bool fast = kfull && nfull && b4;
        if (transB) {
            if (fast) {
#pragma unroll
                for (int i = 0; i < BEL / 4; i++) {
                    int e = tid + i * 256;
                    int n = e >> 2, k4 = (e & 3) << 2;
#pragma unroll
                    for (int j = 0; j < 4; j++)
                        Bs[buf][(k4 + j) * BSTR + n] = f2tf32(bR[i*4+j]);
                }
            } else {
#pragma unroll
                for (int i = 0; i < BEL; i++) {
                    int e = tid + i * 256;
                    int n = e >> 4, k = e & 15;
                    Bs[buf][k * BSTR + n] = f2tf32(bR[i]);
                }
            }
        } else {
            if (fast) {
#pragma unroll
                for (int i = 0; i < BEL / 4; i++) {
                    int e = tid + i * 256;
                    int k = e / (BN / 4), n4 = (e % (BN / 4)) << 2;
                    uint4 w;
                    w.x = f2tf32(bR[i*4+0]); w.y = f2tf32(bR[i*4+1]);
                    w.z = f2tf32(bR[i*4+2]); w.w = f2tf32(bR[i*4+3]);
                    *reinterpret_cast<uint4*>(&Bs[buf][k * BSTR + n4]) = w;
                }
            } else {
#pragma unroll
                for (int i = 0; i < BEL; i++) {
                    int e = tid + i * 256;
                    int k = e / BN, n = e % BN;
                    Bs[buf][k * BSTR + n] = f2tf32(bR[i]);
                }
            }
        }
    };

    bool kf = (BK <= K);
    loadA(0, kf); loadB(0, kf);
    stsA(kf, 0);  stsB(kf, 0);
    __syncthreads();

    int buf = 0;
    for (int it = 0; it < nk; it++) {
        const int k0n = (it + 1) * BK;
        const bool kfn = (k0n + BK <= K);
        if (it + 1 < nk) { loadA(k0n, kfn); loadB(k0n, kfn); }

#pragma unroll
        for (int ks = 0; ks < 2; ks++) {
            const int kk = ks * 8;
            uint32_t af[2][4], bf[NT][2];
#pragma unroll
            for (int mt = 0; mt < 2; mt++) {
                int m0 = wm + mt * 16 + lr;
                af[mt][0] = As[buf][(kk + lc) * ASTR + m0];
                af[mt][1] = As[buf][(kk + lc) * ASTR + m0 + 8];
                af[mt][2] = As[buf][(kk + lc + 4) * ASTR + m0];
                af[mt][3] = As[buf][(kk + lc + 4) * ASTR + m0 + 8];
            }
#pragma unroll
            for (int nt = 0; nt < NT; nt++) {
                int n0 = wn + nt * 8 + lr;
                bf[nt][0] = Bs[buf][(kk + lc) * BSTR + n0];
                bf[nt][1] = Bs[buf][(kk + lc + 4) * BSTR + n0];
            }
#pragma unroll
            for (int mt = 0; mt < 2; mt++)
#pragma unroll
                for (int nt = 0; nt < NT; nt++) {
                    asm volatile(
                        "mma.sync.aligned.m16n8k8.row.col.f32.tf32.tf32.f32 "
                        "{%0,%1,%2,%3}, {%4,%5,%6,%7}, {%8,%9}, {%0,%1,%2,%3};"
                        : "+f"(acc[mt][nt][0]), "+f"(acc[mt][nt][1]),
                          "+f"(acc[mt][nt][2]), "+f"(acc[mt][nt][3])
                        : "r"(af[mt][0]), "r"(af[mt][1]),
                          "r"(af[mt][2]), "r"(af[mt][3]),
                          "r"(bf[nt][0]), "r"(bf[nt][1]));
                }
        }

        if (it + 1 < nk) {
            stsA(kfn, buf ^ 1); stsB(kfn, buf ^ 1);
            __syncthreads();
            buf ^= 1;
        }
    }

    // epilogue (rows always in range; bound N only)
#pragma unroll
    for (int mt = 0; mt < 2; mt++)
#pragma unroll
        for (int nt = 0; nt < NT; nt++) {
            int rb = row0 + wm + mt * 16 + lr;
            int cb = col0 + wn + nt * 8 + lc * 2;
#pragma unroll
            for (int h = 0; h < 2; h++) {
                int r = rb + h * 8;
#pragma unroll
                for (int j = 0; j < 2; j++) {
                    int c = cb + j;
                    if (c >= N) continue;
                    float vv = acc[mt][nt][h * 2 + j] * alpha;
                    if (bias) vv += bias[c];
                    if (flags & FLAG_GELU) vv = gelu_f(vv);
                    long long ci = (long long)r * ldc + c;
                    if (flags & FLAG_ACC) vv += C[ci];
                    C[ci] = vv;
                }
            }
        }
}

// ---------------- weight repack: Wq/Wk/Wv[L,H,E,D] -> Wp[L,E,H*192] ----------------
__global__ void repack_qkv(const float* __restrict__ Wq, const float* __restrict__ Wk,
                           const float* __restrict__ Wv, float* __restrict__ Wp)
{
    long long idx = (long long)blockIdx.x * 256 + threadIdx.x;
    const long long total = (long long)L_ * E_ * QLD_;
    if (idx >= total) return;
    int c = (int)(idx % QLD_);
    long long le = idx / QLD_;
    int e = (int)(le % E_);
    int l = (int)(le / E_);
    int h = c / HB_, r = c % HB_, s = r >> 6, d = r & 63;
    float v = 0.f;
    if (d < D_) {
        const float* W = (s == 0) ? Wq : (s == 1) ? Wk : Wv;
        v = W[(((long long)l * H_ + h) * E_ + e) * D_ + d];
    }
    Wp[idx] = v;
}
__global__ void repack_bias(const float* __restrict__ bq, const float* __restrict__ bk,
                            const float* __restrict__ bv, float* __restrict__ bp)
{
    int idx = blockIdx.x * 256 + threadIdx.x;
    if (idx >= L_ * QLD_) return;
    int c = idx % QLD_, l = idx / QLD_;
    int h = c / HB_, r = c % HB_, s = r >> 6, d = r & 63;
    float v = 0.f;
    if (d < D_) {
        const float* bb = (s == 0) ? bq : (s == 1) ? bk : bv;
        v = bb[((long long)l * H_ + h) * D_ + d];
    }
    bp[idx] = v;
}

// ---------------- pointwise / reduction kernels ----------------
__global__ void embed_kernel(const int* __restrict__ ids,
                             const float* __restrict__ tok,
                             const float* __restrict__ pos,
                             float* __restrict__ x)
{
    int row = blockIdx.x;
    int s = row % S_;
    long long id = ids[row];
    float* xr = x + (long long)row * E_;
    const float* tr = tok + id * E_;
    const float* pr = pos + (long long)s * E_;
    for (int i = threadIdx.x; i < E_; i += blockDim.x)
        xr[i] = tr[i] + pr[i];
}

__global__ void ln_kernel(const float* __restrict__ x,
                          const float* __restrict__ g,
                          const float* __restrict__ b,
                          float* __restrict__ y)
{
    int row = blockIdx.x;
    const float* xr = x + (long long)row * E_;
    float s = 0.f, ss = 0.f;
    for (int i = threadIdx.x; i < E_; i += 128) {
        float v = xr[i];
        s += v; ss += v * v;
    }
#pragma unroll
    for (int o = 16; o > 0; o >>= 1) {
        s  += __shfl_xor_sync(0xffffffffu, s, o);
        ss += __shfl_xor_sync(0xffffffffu, ss, o);
    }
    __shared__ float sh_s[4], sh_ss[4];
    int w = threadIdx.x >> 5;
    if ((threadIdx.x & 31) == 0) { sh_s[w] = s; sh_ss[w] = ss; }
    __syncthreads();
    s  = sh_s[0] + sh_s[1] + sh_s[2] + sh_s[3];
    ss = sh_ss[0] + sh_ss[1] + sh_ss[2] + sh_ss[3];
    float mean = s / E_;
    float var  = ss / E_ - mean * mean;
    float rstd = rsqrtf(var + EPS_);
    float* yr = y + (long long)row * E_;
    for (int i = threadIdx.x; i < E_; i += 128)
        yr[i] = (xr[i] - mean) * rstd * g[i] + b[i];
}

__global__ void softmax_causal(float* __restrict__ attn)
{
    int row = blockIdx.x * 8 + threadIdx.y;
    int lane = threadIdx.x;
    int qi = row % S_;
    float* p = attn + (long long)row * S_;
    int n = qi + 1;
    float mx = -1e30f;
    for (int j = lane; j < n; j += 32) mx = fmaxf(mx, p[j]);
#pragma unroll
    for (int o = 16; o > 0; o >>= 1) mx = fmaxf(mx, __shfl_xor_sync(0xffffffffu, mx, o));
    float sum = 0.f;
    for (int j = lane; j < n; j += 32) {
        float e = expf(p[j] - mx);
        p[j] = e;
        sum += e;
    }
#pragma unroll
    for (int o = 16; o > 0; o >>= 1) sum += __shfl_xor_sync(0xffffffffu, sum, o);
    float inv = 1.f / sum;
    for (int j = lane; j < n; j += 32) p[j] *= inv;
    for (int j = n + lane; j < S_; j += 32) p[j] = 0.f;
}

__global__ void loss_kernel(const float* __restrict__ logits,
                            const int* __restrict__ tgt,
                            float* __restrict__ acc)
{
    int row = blockIdx.x;
    const float* p = logits + (long long)row * V_;
    __shared__ float sh[8];
    float mx = -1e30f;
    for (int j = threadIdx.x; j < V_; j += 256) mx = fmaxf(mx, p[j]);
#pragma unroll
    for (int o = 16; o > 0; o >>= 1) mx = fmaxf(mx, __shfl_xor_sync(0xffffffffu, mx, o));
    int w = threadIdx.x >> 5;
    if ((threadIdx.x & 31) == 0) sh[w] = mx;
    __syncthreads();
    mx = sh[0];
#pragma unroll
    for (int i = 1; i < 8; i++) mx = fmaxf(mx, sh[i]);
    __syncthreads();
    float sum = 0.f;
    for (int j = threadIdx.x; j < V_; j += 256) sum += expf(p[j] - mx);
#pragma unroll
    for (int o = 16; o > 0; o >>= 1) sum += __shfl_xor_sync(0xffffffffu, sum, o);
    if ((threadIdx.x & 31) == 0) sh[w] = sum;
    __syncthreads();
    if (threadIdx.x == 0) {
        float tot = 0.f;
#pragma unroll
        for (int i = 0; i < 8; i++) tot += sh[i];
        float lse = mx + logf(tot);
        atomicAdd(acc, p[tgt[row]] - lse);
    }
}

__global__ void zero_loss(float* a) { *a = 0.f; }
__global__ void fin_loss(const float* a, float* out) { *out = -(*a) / (float)BS_; }

// ---------------- host driver ----------------
typedef long long ll;

static void gemm(bool big, const float* A, const float* Bm, const float* bias, float* C,
                 int M, int N, int Nb, int K, int lda, int ldb, int ldc,
                 int batch, int zdiv,
                 ll sA1, ll sA2, ll sB1, ll sB2, ll sC1, ll sC2,
                 float alpha, int flags)
{
    if (big) {
        dim3 grid((N + 127) / 128, M / 128, batch);
        tc_gemm<128, 8><<<grid, 256>>>(A, Bm, bias, C, M, N, Nb, K, lda, ldb, ldc,
                                       zdiv, sA1, sA2, sB1, sB2, sC1, sC2, alpha, flags);
    } else {
        dim3 grid((N + 63) / 64, M / 128, batch);
        tc_gemm<64, 4><<<grid, 256>>>(A, Bm, bias, C, M, N, Nb, K, lda, ldb, ldc,
                                      zdiv, sA1, sA2, sB1, sB2, sC1, sC2, alpha, flags);
    }
}

extern "C" void kernel_launch(void* const* d_in, const int* in_sizes, int n_in,
                              void* d_out, int out_size)
{
    const int*   input_ids = (const int*)d_in[0];
    const int*   targets   = (const int*)d_in[1];
    const float* tok_emb   = (const float*)d_in[2];
    const float* pos_emb   = (const float*)d_in[3];
    const float* Wq  = (const float*)d_in[4];
    const float* bq  = (const float*)d_in[5];
    const float* Wk  = (const float*)d_in[6];
    const float* bk  = (const float*)d_in[7];
    const float* Wv  = (const float*)d_in[8];
    const float* bv  = (const float*)d_in[9];
    const float* Wc  = (const float*)d_in[10];
    const float* bc  = (const float*)d_in[11];
    const float* g1  = (const float*)d_in[12];
    const float* b1  = (const float*)d_in[13];
    const float* g2  = (const float*)d_in[14];
    const float* b2  = (const float*)d_in[15];
    const float* W1  = (const float*)d_in[16];
    const float* bf1 = (const float*)d_in[17];
    const float* W2  = (const float*)d_in[18];
    const float* bf2 = (const float*)d_in[19];
    const float* gf   = (const float*)d_in[20];
    const float* bfin = (const float*)d_in[21];
    const float* Wout = (const float*)d_in[22];
    const float* bout = (const float*)d_in[23];
    float* out = (float*)d_out;

    float *x, *xn, *qkv, *wqkv, *bqkv, *attn, *ocat, *hbuf, *lossp;
    cudaGetSymbolAddress((void**)&x,    g_x);
    cudaGetSymbolAddress((void**)&xn,   g_xn);
    cudaGetSymbolAddress((void**)&qkv,  g_qkv);
    cudaGetSymbolAddress((void**)&wqkv, g_wqkv);
    cudaGetSymbolAddress((void**)&bqkv, g_bqkv);
    cudaGetSymbolAddress((void**)&attn, g_attn);
    cudaGetSymbolAddress((void**)&ocat, g_ocat);
    cudaGetSymbolAddress((void**)&hbuf, g_h);
    cudaGetSymbolAddress((void**)&lossp, g_loss);

    const float scale = 1.0f / sqrtf((float)D_);

    // weight repack (once per call)
    {
        long long total = (long long)L_ * E_ * QLD_;
        repack_qkv<<<(int)((total + 255) / 256), 256>>>(Wq, Wk, Wv, wqkv);
        repack_bias<<<(L_ * QLD_ + 255) / 256, 256>>>(bq, bk, bv, bqkv);
    }

    embed_kernel<<<BS_, 128>>>(input_ids, tok_emb, pos_emb, x);

    for (int l = 0; l < L_; l++) {
        ln_kernel<<<BS_, 128>>>(x, g1 + l * E_, b1 + l * E_, xn);

        // fused QKV: [4096,384] @ [384,1344]  (padded cols are zero -> zero output)
        gemm(true, xn, wqkv + (ll)l * E_ * QLD_, bqkv + (ll)l * QLD_, qkv,
             BS_, QLD_, QLD_, E_, E_, QLD_, QLD_,
             1, 1, 0, 0, 0, 0, 0, 0, 1.f, 0);

        // scores: z=(b,h);  q at col h*192, k at h*192+64, K=64 (zero-padded)
        gemm(true, qkv, qkv + 64, nullptr, attn,
             S_, S_, S_, 64, QLD_, QLD_, S_,
             B_ * H_, H_,
             (ll)S_ * QLD_, HB_, (ll)S_ * QLD_, HB_,
             (ll)H_ * S_ * S_, (ll)S_ * S_,
             scale, FLAG_TRANSB);

        {
            dim3 blk(32, 8);
            softmax_causal<<<(B_ * H_ * S_) / 8, blk>>>(attn);
        }

        // PV: o[b,s, h*54+d] = attn[b,h] @ v[b,h]   (writes directly into concat layout)
        gemm(false, attn, qkv + 128, nullptr, ocat,
             S_, D_, 64, S_, S_, QLD_, HD_,
             B_ * H_, H_,
             (ll)H_ * S_ * S_, (ll)S_ * S_, (ll)S_ * QLD_, HB_,
             (ll)S_ * HD_, D_,
             1.f, 0);

        // x += ocat @ Wc + bc
        gemm(false, ocat, Wc + (ll)l * HD_ * E_, bc + l * E_, x,
             BS_, E_, E_, HD_, HD_, E_, E_,
             1, 1, 0, 0, 0, 0, 0, 0, 1.f, FLAG_ACC);

        ln_kernel<<<BS_, 128>>>(x, g2 + l * E_, b2 + l * E_, xn);

        // h = gelu(xn @ W1 + bf1)
        gemm(true, xn, W1 + (ll)l * E_ * FF_, bf1 + (ll)l * FF_, hbuf,
             BS_, FF_, FF_, E_, E_, FF_, FF_,
             1, 1, 0, 0, 0, 0, 0, 0, 1.f, FLAG_GELU);

        // x += h @ W2 + bf2
        gemm(false, hbuf, W2 + (ll)l * FF_ * E_, bf2 + l * E_, x,
             BS_, E_, E_, FF_, FF_, E_, E_,
             1, 1, 0, 0, 0, 0, 0, 0, 1.f, FLAG_ACC);
    }

    ln_kernel<<<BS_, 128>>>(x, gf, bfin, xn);
    gemm(true, xn, Wout, bout, out,
         BS_, V_, V_, E_, E_, V_, V_,
         1, 1, 0, 0, 0, 0, 0, 0, 1.f, 0);

    const ll NLOG = (ll)BS_ * V_;
    if ((ll)out_size > NLOG) {
        zero_loss<<<1, 1>>>(lossp);
        loss_kernel<<<BS_, 256>>>(out, targets, lossp);
        fin_loss<<<1, 1>>>(lossp, out + NLOG);
    }
}